// round 1
// baseline (speedup 1.0000x reference)
#include <cuda_runtime.h>
#include <math.h>

#define N_ATOMS 4096
#define N_EDGES 131072
#define NUM_BASIS 8
#define EMBED 64
#define HID 128
#define TP_IN 1152

// ---------------- scratch (static device globals; no allocation) ----------------
__device__ __align__(16) float g_pre[N_ATOMS * TP_IN];     // per-atom aggregated rad (x) sh, layout [atom][s(9)][h(128)]
__device__ __align__(16) float g_agg[N_ATOMS * HID];
__device__ __align__(16) float g_upd[N_ATOMS * HID];
__device__ __align__(16) float g_qkv[N_ATOMS * 3 * HID];
__device__ __align__(16) float g_att[N_ATOMS * HID];
__device__ __align__(16) float g_tpw[TP_IN * HID];         // permuted tp_w matching g_pre layout
__device__ __align__(16) float g_wqkvT[HID * 3 * HID];     // attn_w_in transposed -> [d][j]
__device__ __align__(16) float g_woutT[HID * HID];         // attn_w_out transposed -> [d][j]
__device__ int g_count[N_ATOMS];
__device__ int g_offset[N_ATOMS + 1];
__device__ int g_cursor[N_ATOMS];
__device__ int g_eperm[N_EDGES];

// ---------------- CSR build ----------------
__global__ void zero_kernel() {
    int i = blockIdx.x * blockDim.x + threadIdx.x;
    if (i < N_ATOMS) g_count[i] = 0;
}

__global__ void hist_kernel(const int* __restrict__ dst) {
    int i = blockIdx.x * blockDim.x + threadIdx.x;
    if (i < N_EDGES) atomicAdd(&g_count[dst[i]], 1);
}

__global__ void scan_kernel() {
    __shared__ int buf0[N_ATOMS];
    __shared__ int buf1[N_ATOMS];
    int t = threadIdx.x;
    for (int i = t; i < N_ATOMS; i += 1024) buf0[i] = g_count[i];
    __syncthreads();
    int* cur = buf0;
    int* nxt = buf1;
    for (int off = 1; off < N_ATOMS; off <<= 1) {
        for (int i = t; i < N_ATOMS; i += 1024) {
            int v = cur[i];
            if (i >= off) v += cur[i - off];
            nxt[i] = v;
        }
        __syncthreads();
        int* tmp = cur; cur = nxt; nxt = tmp;
    }
    // 12 iterations (even) -> result back in buf0 == cur
    for (int i = t; i < N_ATOMS; i += 1024) {
        g_offset[i + 1] = cur[i];
        g_cursor[i] = (i == 0) ? 0 : cur[i - 1];
    }
    if (t == 0) g_offset[0] = 0;
}

__global__ void scatter_kernel(const int* __restrict__ dst) {
    int i = blockIdx.x * blockDim.x + threadIdx.x;
    if (i < N_EDGES) {
        int p = atomicAdd(&g_cursor[dst[i]], 1);
        g_eperm[p] = i;
    }
}

// ---------------- weight prep: permute tp_w, transpose attn weights ----------------
__global__ void prep_kernel(const float* __restrict__ tpw,
                            const float* __restrict__ win,
                            const float* __restrict__ wout) {
    int idx = blockIdx.x * blockDim.x + threadIdx.x;
    int stride = gridDim.x * blockDim.x;
    for (int i = idx; i < TP_IN * HID; i += stride) {
        int rp = i >> 7;   // our row index = s*128 + h
        int c = i & 127;
        int s = rp >> 7;
        int h = rp & 127;
        int row;
        if (s == 0)      row = h;
        else if (s <= 3) row = 128 + h * 3 + (s - 1);
        else             row = 512 + h * 5 + (s - 4);
        g_tpw[i] = tpw[row * HID + c];
    }
    for (int i = idx; i < HID * 3 * HID; i += stride) {
        int d = i / 384, j = i % 384;
        g_wqkvT[i] = win[j * HID + d];
    }
    for (int i = idx; i < HID * HID; i += stride) {
        int d = i >> 7, j = i & 127;
        g_woutT[i] = wout[j * HID + d];
    }
}

// ---------------- per-atom edge aggregation: rad MLP + outer(rad, sh) sum ----------------
// grid 1024 blocks x 128 threads; each warp handles one atom (4 atoms/block).
__global__ void __launch_bounds__(128) edge_agg_kernel(
    const float* __restrict__ ev, const float* __restrict__ el,
    const float* __restrict__ rw1, const float* __restrict__ rb1,
    const float* __restrict__ rw2, const float* __restrict__ rb2) {
    __shared__ float w1s[8 * 64];
    __shared__ float w2s[64 * 128];
    __shared__ float b1s[64];
    __shared__ float b2s[128];
    __shared__ float r1s[4][64];

    int t = threadIdx.x;
    for (int i = t; i < 512; i += 128) w1s[i] = rw1[i];
    for (int i = t; i < 8192; i += 128) w2s[i] = rw2[i];
    if (t < 64) b1s[t] = rb1[t];
    b2s[t] = rb2[t];
    __syncthreads();

    int w = t >> 5, lane = t & 31;
    int atom = blockIdx.x * 4 + w;
    int start = g_offset[atom];
    int end = g_offset[atom + 1];

    float acc[4][9];
#pragma unroll
    for (int k = 0; k < 4; k++)
#pragma unroll
        for (int s = 0; s < 9; s++) acc[k][s] = 0.f;

    const float FP = 3.14159265358979323846f / 6.0f;

    for (int idx = start; idx < end; ++idx) {
        int e = g_eperm[idx];
        float vx = ev[e * 3 + 0], vy = ev[e * 3 + 1], vz = ev[e * 3 + 2];
        float d = el[e];
        float r = sqrtf(vx * vx + vy * vy + vz * vz) + 1e-8f;
        float inv = 1.f / r;
        float x = vx * inv, y = vy * inv, z = vz * inv;
        float sh[9];
        sh[0] = 1.f; sh[1] = y; sh[2] = z; sh[3] = x;
        sh[4] = 3.f * z * z - 1.f; sh[5] = x * z; sh[6] = y * z;
        sh[7] = x * y; sh[8] = x * x - y * y;

        float cut = 0.5f * (cosf(d * FP) + 1.f) * (d < 6.0f ? 1.f : 0.f);
        float invd = cut / d;
        float rbf[8];
#pragma unroll
        for (int i = 0; i < 8; i++) rbf[i] = sinf(d * (FP * (i + 1))) * invd;

        // rad1 = silu(rbf @ w1 + b1): lane computes cols lane, lane+32
        float a0 = b1s[lane], a1 = b1s[lane + 32];
#pragma unroll
        for (int i = 0; i < 8; i++) {
            a0 += rbf[i] * w1s[i * 64 + lane];
            a1 += rbf[i] * w1s[i * 64 + lane + 32];
        }
        a0 = a0 / (1.f + __expf(-a0));
        a1 = a1 / (1.f + __expf(-a1));
        r1s[w][lane] = a0;
        r1s[w][lane + 32] = a1;
        __syncwarp();

        // rad2 = silu(rad1 @ w2 + b2): lane computes h = k*32+lane, k<4
        float r2[4];
#pragma unroll
        for (int k = 0; k < 4; k++) r2[k] = b2s[k * 32 + lane];
#pragma unroll 8
        for (int j = 0; j < 64; j++) {
            float rj = r1s[w][j];
#pragma unroll
            for (int k = 0; k < 4; k++) r2[k] += rj * w2s[j * 128 + k * 32 + lane];
        }
        __syncwarp();
#pragma unroll
        for (int k = 0; k < 4; k++) {
            float v = r2[k];
            v = v / (1.f + __expf(-v));
#pragma unroll
            for (int s = 0; s < 9; s++) acc[k][s] += v * sh[s];
        }
    }

#pragma unroll
    for (int k = 0; k < 4; k++)
#pragma unroll
        for (int s = 0; s < 9; s++)
            g_pre[(size_t)atom * TP_IN + s * 128 + k * 32 + lane] = acc[k][s];
}

// ---------------- agg = g_pre @ g_tpw + tp_b : [4096,1152]x[1152,128] ----------------
// block: 32 rows x 128 cols, 128 threads; thread = (col-quad, row-group of 8)
__global__ void __launch_bounds__(128) tp_gemm_kernel(const float* __restrict__ tpb) {
    __shared__ float sh[32 * 64];
    int t = threadIdx.x;
    int cq = t & 31;   // columns 4*cq .. 4*cq+3
    int rg = t >> 5;   // rows rg*8 .. rg*8+7
    int row0 = blockIdx.x * 32;
    float acc[8][4];
#pragma unroll
    for (int r = 0; r < 8; r++)
#pragma unroll
        for (int c = 0; c < 4; c++) acc[r][c] = 0.f;

    for (int kc = 0; kc < 18; kc++) {
        __syncthreads();
        for (int i = t; i < 2048; i += 128) {
            int r = i >> 6, k = i & 63;
            sh[i] = g_pre[(size_t)(row0 + r) * TP_IN + kc * 64 + k];
        }
        __syncthreads();
#pragma unroll 4
        for (int k = 0; k < 64; k++) {
            float4 wv = *(const float4*)(g_tpw + (size_t)(kc * 64 + k) * HID + cq * 4);
#pragma unroll
            for (int r = 0; r < 8; r++) {
                float sv = sh[(rg * 8 + r) * 64 + k];
                acc[r][0] += sv * wv.x;
                acc[r][1] += sv * wv.y;
                acc[r][2] += sv * wv.z;
                acc[r][3] += sv * wv.w;
            }
        }
    }
    float4 b4 = *(const float4*)(tpb + cq * 4);
#pragma unroll
    for (int r = 0; r < 8; r++) {
        float4 o;
        o.x = acc[r][0] + b4.x; o.y = acc[r][1] + b4.y;
        o.z = acc[r][2] + b4.z; o.w = acc[r][3] + b4.w;
        *(float4*)(g_agg + (size_t)(row0 + rg * 8 + r) * HID + cq * 4) = o;
    }
}

// ---------------- upd = silu([node|agg] @ msg_w1 + b1) @ msg_w2 + b2 ----------------
__global__ void __launch_bounds__(128) upd_kernel(
    const int* __restrict__ an, const float* __restrict__ embed,
    const float* __restrict__ mw1, const float* __restrict__ mb1,
    const float* __restrict__ mw2, const float* __restrict__ mb2) {
    __shared__ float comb[16][192];
    __shared__ float t1[16][128];
    __shared__ int ans[16];
    int t = threadIdx.x;
    int base = blockIdx.x * 16;
    if (t < 16) ans[t] = an[base + t];
    __syncthreads();
    for (int i = t; i < 16 * 64; i += 128) {
        int a = i >> 6, d = i & 63;
        comb[a][d] = embed[ans[a] * 64 + d];
    }
    for (int i = t; i < 16 * 128; i += 128) {
        int a = i >> 7, d = i & 127;
        comb[a][64 + d] = g_agg[(size_t)(base + a) * HID + d];
    }
    __syncthreads();
    float acc[16];
#pragma unroll
    for (int a = 0; a < 16; a++) acc[a] = 0.f;
    for (int d = 0; d < 192; d++) {
        float wv = mw1[d * HID + t];
#pragma unroll
        for (int a = 0; a < 16; a++) acc[a] += comb[a][d] * wv;
    }
    float b1 = mb1[t];
#pragma unroll
    for (int a = 0; a < 16; a++) {
        float v = acc[a] + b1;
        t1[a][t] = v / (1.f + __expf(-v));
    }
    __syncthreads();
#pragma unroll
    for (int a = 0; a < 16; a++) acc[a] = 0.f;
    for (int d = 0; d < 128; d++) {
        float wv = mw2[d * HID + t];
#pragma unroll
        for (int a = 0; a < 16; a++) acc[a] += t1[a][d] * wv;
    }
    float b2 = mb2[t];
#pragma unroll
    for (int a = 0; a < 16; a++)
        g_upd[(size_t)(base + a) * HID + t] = acc[a] + b2;
}

// ---------------- qkv = upd @ attn_w_in^T + b ----------------
__global__ void __launch_bounds__(384) qkv_kernel(const float* __restrict__ bqkv) {
    __shared__ float u[16][128];
    int t = threadIdx.x;
    int base = blockIdx.x * 16;
    for (int i = t; i < 2048; i += 384) {
        int a = i >> 7, d = i & 127;
        u[a][d] = g_upd[(size_t)(base + a) * HID + d];
    }
    __syncthreads();
    float acc[16];
#pragma unroll
    for (int a = 0; a < 16; a++) acc[a] = 0.f;
    for (int d = 0; d < 128; d++) {
        float wv = g_wqkvT[d * 384 + t];
#pragma unroll
        for (int a = 0; a < 16; a++) acc[a] += u[a][d] * wv;
    }
    float b = bqkv[t];
#pragma unroll
    for (int a = 0; a < 16; a++)
        g_qkv[(size_t)(base + a) * 384 + t] = acc[a] + b;
}

// ---------------- dense softmax attention (flash style, fp32) ----------------
// grid (64 q-tiles, 4 heads) x 128 threads. Thread pair (2t,2t+1) owns one q-row,
// each half handles 32 kv columns per 64-wide tile.
__global__ void __launch_bounds__(128) attn_kernel() {
    __shared__ float Ksh[64 * 32];
    __shared__ float Vsh[64 * 32];
    int t = threadIdx.x;
    int row = t >> 1, half = t & 1;
    int head = blockIdx.y;
    int qrow = blockIdx.x * 64 + row;
    const float* qb = g_qkv + (size_t)qrow * 384 + head * 32;
    float q[32];
#pragma unroll
    for (int d = 0; d < 32; d++) q[d] = qb[d];
    float acc[32];
#pragma unroll
    for (int d = 0; d < 32; d++) acc[d] = 0.f;
    float m = -1e30f, l = 0.f;
    const float scale = 0.17677669529663687f;  // 1/sqrt(32)

    for (int kt = 0; kt < 64; kt++) {
        __syncthreads();
        const float* kb = g_qkv + (size_t)(kt * 64) * 384 + 128 + head * 32;
        for (int i = t; i < 512; i += 128) {
            int r = i >> 3;
            int d4 = (i & 7) * 4;
            float4 kv = *(const float4*)(kb + r * 384 + d4);
            *(float4*)(Ksh + r * 32 + d4) = kv;
            float4 vv = *(const float4*)(kb + 128 + r * 384 + d4);
            *(float4*)(Vsh + r * 32 + d4) = vv;
        }
        __syncthreads();

        float s[32];
        const int cb = half * 32;
#pragma unroll 4
        for (int j = 0; j < 32; j++) {
            const float4* kr = (const float4*)(Ksh + (cb + j) * 32);
            float sv = 0.f;
#pragma unroll
            for (int d4 = 0; d4 < 8; d4++) {
                float4 k4 = kr[d4];
                sv += q[d4 * 4 + 0] * k4.x + q[d4 * 4 + 1] * k4.y +
                      q[d4 * 4 + 2] * k4.z + q[d4 * 4 + 3] * k4.w;
            }
            s[j] = sv * scale;
        }
        float tmax = s[0];
#pragma unroll
        for (int j = 1; j < 32; j++) tmax = fmaxf(tmax, s[j]);
        tmax = fmaxf(tmax, __shfl_xor_sync(0xffffffffu, tmax, 1));
        float mnew = fmaxf(m, tmax);
        float corr = __expf(m - mnew);
        l *= corr;
#pragma unroll
        for (int d = 0; d < 32; d++) acc[d] *= corr;
#pragma unroll
        for (int j = 0; j < 32; j++) {
            float p = __expf(s[j] - mnew);
            s[j] = p;
            l += p;
        }
        m = mnew;
#pragma unroll 4
        for (int j = 0; j < 32; j++) {
            const float4* vr = (const float4*)(Vsh + (cb + j) * 32);
            float p = s[j];
#pragma unroll
            for (int d4 = 0; d4 < 8; d4++) {
                float4 v4 = vr[d4];
                acc[d4 * 4 + 0] += p * v4.x;
                acc[d4 * 4 + 1] += p * v4.y;
                acc[d4 * 4 + 2] += p * v4.z;
                acc[d4 * 4 + 3] += p * v4.w;
            }
        }
    }
    l += __shfl_xor_sync(0xffffffffu, l, 1);
#pragma unroll
    for (int d = 0; d < 32; d++) acc[d] += __shfl_xor_sync(0xffffffffu, acc[d], 1);
    float inv = 1.f / l;
    float* ob = g_att + (size_t)qrow * HID + head * 32 + half * 16;
#pragma unroll
    for (int d = 0; d < 16; d++) ob[d] = acc[half * 16 + d] * inv;
}

// ---------------- epilogue: attn out-proj, gate, mix, final linear ----------------
__global__ void __launch_bounds__(128) epi_kernel(
    const float* __restrict__ bout_att,
    const float* __restrict__ gw, const float* __restrict__ gb,
    const float* __restrict__ ow, const float* __restrict__ ob,
    float* __restrict__ out) {
    __shared__ float att[16][128];
    __shared__ float upd[16][128];
    __shared__ float osh[16][128];
    int t = threadIdx.x;
    int base = blockIdx.x * 16;
    for (int i = t; i < 2048; i += 128) {
        int a = i >> 7, d = i & 127;
        att[a][d] = g_att[(size_t)(base + a) * HID + d];
        upd[a][d] = g_upd[(size_t)(base + a) * HID + d];
    }
    __syncthreads();
    float ap[16];
#pragma unroll
    for (int a = 0; a < 16; a++) ap[a] = 0.f;
    for (int d = 0; d < 128; d++) {
        float wv = g_woutT[d * HID + t];
#pragma unroll
        for (int a = 0; a < 16; a++) ap[a] += att[a][d] * wv;
    }
    float ba = bout_att[t];
    float gacc[16];
#pragma unroll
    for (int a = 0; a < 16; a++) gacc[a] = 0.f;
    for (int d = 0; d < 128; d++) {
        float wv = gw[d * HID + t];
#pragma unroll
        for (int a = 0; a < 16; a++) gacc[a] += upd[a][d] * wv;
    }
    float bg = gb[t];
#pragma unroll
    for (int a = 0; a < 16; a++) {
        float g = 1.f / (1.f + __expf(-(gacc[a] + bg)));
        osh[a][t] = g * (ap[a] + ba) + (1.f - g) * upd[a][t];
    }
    __syncthreads();
    float f[16];
#pragma unroll
    for (int a = 0; a < 16; a++) f[a] = 0.f;
    for (int d = 0; d < 128; d++) {
        float wv = ow[d * HID + t];
#pragma unroll
        for (int a = 0; a < 16; a++) f[a] += osh[a][d] * wv;
    }
    float bo = ob[t];
#pragma unroll
    for (int a = 0; a < 16; a++)
        out[(size_t)(base + a) * HID + t] = f[a] + bo;
}

// ---------------- launch ----------------
extern "C" void kernel_launch(void* const* d_in, const int* in_sizes, int n_in,
                              void* d_out, int out_size) {
    const int* an = (const int*)d_in[0];
    const int* ei = (const int*)d_in[2];
    const float* ev = (const float*)d_in[3];
    const float* el = (const float*)d_in[4];
    const float* embed = (const float*)d_in[5];
    const float* rw1 = (const float*)d_in[6];
    const float* rb1 = (const float*)d_in[7];
    const float* rw2 = (const float*)d_in[8];
    const float* rb2 = (const float*)d_in[9];
    const float* tpw = (const float*)d_in[10];
    const float* tpb = (const float*)d_in[11];
    const float* mw1 = (const float*)d_in[12];
    const float* mb1 = (const float*)d_in[13];
    const float* mw2 = (const float*)d_in[14];
    const float* mb2 = (const float*)d_in[15];
    const float* win = (const float*)d_in[16];
    const float* bin = (const float*)d_in[17];
    const float* wout = (const float*)d_in[18];
    const float* bout = (const float*)d_in[19];
    const float* gw = (const float*)d_in[20];
    const float* gb = (const float*)d_in[21];
    const float* ow = (const float*)d_in[22];
    const float* obv = (const float*)d_in[23];
    float* out = (float*)d_out;

    const int* dst = ei + N_EDGES;  // edge_index[1]

    zero_kernel<<<16, 256>>>();
    hist_kernel<<<256, 512>>>(dst);
    prep_kernel<<<256, 256>>>(tpw, win, wout);
    scan_kernel<<<1, 1024>>>();
    scatter_kernel<<<256, 512>>>(dst);
    edge_agg_kernel<<<1024, 128>>>(ev, el, rw1, rb1, rw2, rb2);
    tp_gemm_kernel<<<128, 128>>>(tpb);
    upd_kernel<<<256, 128>>>(an, embed, mw1, mb1, mw2, mb2);
    qkv_kernel<<<256, 384>>>(bin);
    attn_kernel<<<dim3(64, 4), 128>>>();
    epi_kernel<<<256, 128>>>(bout, gw, gb, ow, obv, out);
}

// round 2
// speedup vs baseline: 2.6424x; 2.6424x over previous
#include <cuda_runtime.h>
#include <math.h>
#include <stdint.h>

#define N_ATOMS 4096
#define N_EDGES 131072
#define EMBED 64
#define HID 128
#define TP_IN 1152
#define NBINS 4096
#define D_LO 0.4f
#define D_HI 6.0f

// ---------------- scratch ----------------
__device__ __align__(16) float g_pre[N_ATOMS * TP_IN];
__device__ __align__(16) float g_agg[N_ATOMS * HID];
__device__ __align__(16) float g_upd[N_ATOMS * HID];
__device__ __align__(16) float g_qkv[N_ATOMS * 3 * HID];
__device__ __align__(16) float g_att[N_ATOMS * HID];
__device__ __align__(16) float g_tpw[TP_IN * HID];
__device__ __align__(16) float g_wqkvT[HID * 3 * HID];
__device__ __align__(16) float g_woutT[HID * HID];
__device__ __align__(16) float g_radtab[(NBINS + 1) * HID];
__device__ int g_count[N_ATOMS];
__device__ int g_offset[N_ATOMS + 1];
__device__ int g_cursor[N_ATOMS];
__device__ int g_eperm[N_EDGES];

// ---------------- CSR build ----------------
__global__ void zero_kernel() {
    int i = blockIdx.x * blockDim.x + threadIdx.x;
    if (i < N_ATOMS) g_count[i] = 0;
}

__global__ void hist_kernel(const int* __restrict__ dst) {
    int i = blockIdx.x * blockDim.x + threadIdx.x;
    if (i < N_EDGES) atomicAdd(&g_count[dst[i]], 1);
}

__global__ void scan_kernel() {
    __shared__ int buf0[N_ATOMS];
    __shared__ int buf1[N_ATOMS];
    int t = threadIdx.x;
    for (int i = t; i < N_ATOMS; i += 1024) buf0[i] = g_count[i];
    __syncthreads();
    int* cur = buf0;
    int* nxt = buf1;
    for (int off = 1; off < N_ATOMS; off <<= 1) {
        for (int i = t; i < N_ATOMS; i += 1024) {
            int v = cur[i];
            if (i >= off) v += cur[i - off];
            nxt[i] = v;
        }
        __syncthreads();
        int* tmp = cur; cur = nxt; nxt = tmp;
    }
    for (int i = t; i < N_ATOMS; i += 1024) {
        g_offset[i + 1] = cur[i];
        g_cursor[i] = (i == 0) ? 0 : cur[i - 1];
    }
    if (t == 0) g_offset[0] = 0;
}

__global__ void scatter_kernel(const int* __restrict__ dst) {
    int i = blockIdx.x * blockDim.x + threadIdx.x;
    if (i < N_EDGES) {
        int p = atomicAdd(&g_cursor[dst[i]], 1);
        g_eperm[p] = i;
    }
}

// ---------------- weight prep ----------------
__global__ void prep_kernel(const float* __restrict__ tpw,
                            const float* __restrict__ win,
                            const float* __restrict__ wout) {
    int idx = blockIdx.x * blockDim.x + threadIdx.x;
    int stride = gridDim.x * blockDim.x;
    for (int i = idx; i < TP_IN * HID; i += stride) {
        int rp = i >> 7;
        int c = i & 127;
        int s = rp >> 7;
        int h = rp & 127;
        int row;
        if (s == 0)      row = h;
        else if (s <= 3) row = 128 + h * 3 + (s - 1);
        else             row = 512 + h * 5 + (s - 4);
        g_tpw[i] = tpw[row * HID + c];
    }
    for (int i = idx; i < HID * 3 * HID; i += stride) {
        int d = i / 384, j = i % 384;
        g_wqkvT[i] = win[j * HID + d];
    }
    for (int i = idx; i < HID * HID; i += stride) {
        int d = i >> 7, j = i & 127;
        g_woutT[i] = wout[j * HID + d];
    }
}

// ---------------- radial table: rad(d) for NBINS+1 grid points ----------------
// warp per bin; exact trig + MLP once per bin instead of per edge.
__global__ void __launch_bounds__(128) radtab_kernel(
    const float* __restrict__ rw1, const float* __restrict__ rb1,
    const float* __restrict__ rw2, const float* __restrict__ rb2) {
    __shared__ float w1s[8 * 64];
    __shared__ float w2s[64 * 128];
    __shared__ float b1s[64];
    __shared__ float b2s[128];
    __shared__ float r1s[4][64];

    int t = threadIdx.x;
    for (int i = t; i < 512; i += 128) w1s[i] = rw1[i];
    for (int i = t; i < 8192; i += 128) w2s[i] = rw2[i];
    if (t < 64) b1s[t] = rb1[t];
    b2s[t] = rb2[t];
    __syncthreads();

    int w = t >> 5, lane = t & 31;
    int bin = blockIdx.x * 4 + w;
    if (bin > NBINS) return;

    const float h = (D_HI - D_LO) / (float)NBINS;
    float d = D_LO + bin * h;
    const float FP = 3.14159265358979323846f / 6.0f;

    float cut = 0.5f * (cosf(d * FP) + 1.f) * (d < 6.0f ? 1.f : 0.f);
    float invd = cut / d;
    float rbf[8];
#pragma unroll
    for (int i = 0; i < 8; i++) rbf[i] = sinf(d * (FP * (i + 1))) * invd;

    float a0 = b1s[lane], a1 = b1s[lane + 32];
#pragma unroll
    for (int i = 0; i < 8; i++) {
        a0 += rbf[i] * w1s[i * 64 + lane];
        a1 += rbf[i] * w1s[i * 64 + lane + 32];
    }
    a0 = a0 / (1.f + __expf(-a0));
    a1 = a1 / (1.f + __expf(-a1));
    r1s[w][lane] = a0;
    r1s[w][lane + 32] = a1;
    __syncwarp();

    float r2[4];
#pragma unroll
    for (int k = 0; k < 4; k++) r2[k] = b2s[k * 32 + lane];
#pragma unroll 8
    for (int j = 0; j < 64; j++) {
        float rj = r1s[w][j];
#pragma unroll
        for (int k = 0; k < 4; k++) r2[k] += rj * w2s[j * 128 + k * 32 + lane];
    }
#pragma unroll
    for (int k = 0; k < 4; k++) {
        float v = r2[k];
        v = v / (1.f + __expf(-v));
        g_radtab[bin * HID + k * 32 + lane] = v;
    }
}

// ---------------- per-atom edge aggregation via table lerp ----------------
__global__ void __launch_bounds__(128) edge_agg_kernel(
    const float* __restrict__ ev, const float* __restrict__ el) {
    int t = threadIdx.x;
    int w = t >> 5, lane = t & 31;
    int atom = blockIdx.x * 4 + w;
    int start = g_offset[atom];
    int end = g_offset[atom + 1];

    float acc[4][9];
#pragma unroll
    for (int k = 0; k < 4; k++)
#pragma unroll
        for (int s = 0; s < 9; s++) acc[k][s] = 0.f;

    const float INV_H = (float)NBINS / (D_HI - D_LO);

    for (int idx = start; idx < end; ++idx) {
        int e = g_eperm[idx];
        float vx = __ldg(ev + e * 3 + 0);
        float vy = __ldg(ev + e * 3 + 1);
        float vz = __ldg(ev + e * 3 + 2);
        float d = __ldg(el + e);
        float r = sqrtf(vx * vx + vy * vy + vz * vz) + 1e-8f;
        float inv = 1.f / r;
        float x = vx * inv, y = vy * inv, z = vz * inv;
        float sh[9];
        sh[0] = 1.f; sh[1] = y; sh[2] = z; sh[3] = x;
        sh[4] = 3.f * z * z - 1.f; sh[5] = x * z; sh[6] = y * z;
        sh[7] = x * y; sh[8] = x * x - y * y;

        float tt = (d - D_LO) * INV_H;
        int i0 = (int)tt;
        i0 = min(max(i0, 0), NBINS - 1);
        float f = tt - (float)i0;
        const float* r0 = g_radtab + (size_t)i0 * HID;

#pragma unroll
        for (int k = 0; k < 4; k++) {
            int c = k * 32 + lane;
            float lo = r0[c];
            float hi = r0[c + HID];
            float ra = fmaf(f, hi - lo, lo);
#pragma unroll
            for (int s = 0; s < 9; s++) acc[k][s] += ra * sh[s];
        }
    }

#pragma unroll
    for (int k = 0; k < 4; k++)
#pragma unroll
        for (int s = 0; s < 9; s++)
            g_pre[(size_t)atom * TP_IN + s * 128 + k * 32 + lane] = acc[k][s];
}

// ---------------- agg = g_pre @ g_tpw + deg*tp_b ----------------
__global__ void __launch_bounds__(128) tp_gemm_kernel(const float* __restrict__ tpb) {
    __shared__ float sh[32 * 64];
    int t = threadIdx.x;
    int cq = t & 31;
    int rg = t >> 5;
    int row0 = blockIdx.x * 32;
    float acc[8][4];
#pragma unroll
    for (int r = 0; r < 8; r++)
#pragma unroll
        for (int c = 0; c < 4; c++) acc[r][c] = 0.f;

    for (int kc = 0; kc < 18; kc++) {
        __syncthreads();
        for (int i = t; i < 2048; i += 128) {
            int r = i >> 6, k = i & 63;
            sh[i] = g_pre[(size_t)(row0 + r) * TP_IN + kc * 64 + k];
        }
        __syncthreads();
#pragma unroll 4
        for (int k = 0; k < 64; k++) {
            float4 wv = *(const float4*)(g_tpw + (size_t)(kc * 64 + k) * HID + cq * 4);
#pragma unroll
            for (int r = 0; r < 8; r++) {
                float sv = sh[(rg * 8 + r) * 64 + k];
                acc[r][0] += sv * wv.x;
                acc[r][1] += sv * wv.y;
                acc[r][2] += sv * wv.z;
                acc[r][3] += sv * wv.w;
            }
        }
    }
    float4 b4 = *(const float4*)(tpb + cq * 4);
#pragma unroll
    for (int r = 0; r < 8; r++) {
        int row = row0 + rg * 8 + r;
        float deg = (float)g_count[row];   // per-edge bias sums to deg * b
        float4 o;
        o.x = acc[r][0] + deg * b4.x; o.y = acc[r][1] + deg * b4.y;
        o.z = acc[r][2] + deg * b4.z; o.w = acc[r][3] + deg * b4.w;
        *(float4*)(g_agg + (size_t)row * HID + cq * 4) = o;
    }
}

// ---------------- upd MLP ----------------
__global__ void __launch_bounds__(128) upd_kernel(
    const int* __restrict__ an, const float* __restrict__ embed,
    const float* __restrict__ mw1, const float* __restrict__ mb1,
    const float* __restrict__ mw2, const float* __restrict__ mb2) {
    __shared__ float comb[16][192];
    __shared__ float t1[16][128];
    __shared__ int ans[16];
    int t = threadIdx.x;
    int base = blockIdx.x * 16;
    if (t < 16) ans[t] = an[base + t];
    __syncthreads();
    for (int i = t; i < 16 * 64; i += 128) {
        int a = i >> 6, d = i & 63;
        comb[a][d] = embed[ans[a] * 64 + d];
    }
    for (int i = t; i < 16 * 128; i += 128) {
        int a = i >> 7, d = i & 127;
        comb[a][64 + d] = g_agg[(size_t)(base + a) * HID + d];
    }
    __syncthreads();
    float acc[16];
#pragma unroll
    for (int a = 0; a < 16; a++) acc[a] = 0.f;
    for (int d = 0; d < 192; d++) {
        float wv = mw1[d * HID + t];
#pragma unroll
        for (int a = 0; a < 16; a++) acc[a] += comb[a][d] * wv;
    }
    float b1 = mb1[t];
#pragma unroll
    for (int a = 0; a < 16; a++) {
        float v = acc[a] + b1;
        t1[a][t] = v / (1.f + __expf(-v));
    }
    __syncthreads();
#pragma unroll
    for (int a = 0; a < 16; a++) acc[a] = 0.f;
    for (int d = 0; d < 128; d++) {
        float wv = mw2[d * HID + t];
#pragma unroll
        for (int a = 0; a < 16; a++) acc[a] += t1[a][d] * wv;
    }
    float b2 = mb2[t];
#pragma unroll
    for (int a = 0; a < 16; a++)
        g_upd[(size_t)(base + a) * HID + t] = acc[a] + b2;
}

// ---------------- qkv ----------------
__global__ void __launch_bounds__(384) qkv_kernel(const float* __restrict__ bqkv) {
    __shared__ float u[16][128];
    int t = threadIdx.x;
    int base = blockIdx.x * 16;
    for (int i = t; i < 2048; i += 384) {
        int a = i >> 7, d = i & 127;
        u[a][d] = g_upd[(size_t)(base + a) * HID + d];
    }
    __syncthreads();
    float acc[16];
#pragma unroll
    for (int a = 0; a < 16; a++) acc[a] = 0.f;
    for (int d = 0; d < 128; d++) {
        float wv = g_wqkvT[d * 384 + t];
#pragma unroll
        for (int a = 0; a < 16; a++) acc[a] += u[a][d] * wv;
    }
    float b = bqkv[t];
#pragma unroll
    for (int a = 0; a < 16; a++)
        g_qkv[(size_t)(base + a) * 384 + t] = acc[a] + b;
}

// ---------------- tf32 mma flash attention ----------------
__device__ __forceinline__ void mma_tf32(float* d, const uint32_t* a, const uint32_t* b) {
    asm volatile(
        "mma.sync.aligned.m16n8k8.row.col.f32.tf32.tf32.f32 "
        "{%0,%1,%2,%3},{%4,%5,%6,%7},{%8,%9},{%0,%1,%2,%3};\n"
        : "+f"(d[0]), "+f"(d[1]), "+f"(d[2]), "+f"(d[3])
        : "r"(a[0]), "r"(a[1]), "r"(a[2]), "r"(a[3]), "r"(b[0]), "r"(b[1]));
}

__device__ __forceinline__ void split_tf32(float x, uint32_t& hi, uint32_t& lo) {
    uint32_t xb = __float_as_uint(x);
    uint32_t h = xb & 0xFFFFE000u;
    hi = h;
    lo = __float_as_uint(x - __uint_as_float(h));
}

__device__ __forceinline__ float trunc_tf32(float x) {
    return __uint_as_float(__float_as_uint(x) & 0xFFFFE000u);
}

// block: 64 q rows, 4 warps (warp = one m16 tile). KV tile = 32 keys.
// smem strides: Ks 36 (banks 4g+tg distinct), Vs 40 (banks 8tg+g distinct), Ps 36.
__global__ void __launch_bounds__(128) attn_mma_kernel() {
    __shared__ float Ks[32 * 36];
    __shared__ float Vs[32 * 40];
    __shared__ float Ps[4 * 16 * 36];
    const int t = threadIdx.x;
    const int warp = t >> 5, lane = t & 31;
    const int g = lane >> 2, tg = lane & 3;
    const int head = blockIdx.y;
    const int q0 = blockIdx.x * 64 + warp * 16;
    const float scale = 0.17677669529663687f;  // 1/sqrt(32)

    // Q fragments (resident), split into hi/lo tf32 for fp32-grade scores
    uint32_t qhi[4][4], qlo[4][4];
#pragma unroll
    for (int kk = 0; kk < 4; kk++) {
        const float* qp = g_qkv + (size_t)(q0 + g) * 384 + head * 32 + kk * 8;
        const float* qp8 = qp + 8 * 384;
        float a0 = qp[tg] * scale;
        float a1 = qp8[tg] * scale;
        float a2 = qp[tg + 4] * scale;
        float a3 = qp8[tg + 4] * scale;
        split_tf32(a0, qhi[kk][0], qlo[kk][0]);
        split_tf32(a1, qhi[kk][1], qlo[kk][1]);
        split_tf32(a2, qhi[kk][2], qlo[kk][2]);
        split_tf32(a3, qhi[kk][3], qlo[kk][3]);
    }

    float O[4][4];
#pragma unroll
    for (int nn = 0; nn < 4; nn++)
#pragma unroll
        for (int i = 0; i < 4; i++) O[nn][i] = 0.f;
    float m0 = -1e30f, m1 = -1e30f, l0 = 0.f, l1 = 0.f;
    float* Pw = Ps + warp * (16 * 36);

    for (int kt = 0; kt < 128; ++kt) {
        __syncthreads();
#pragma unroll
        for (int i = t; i < 256; i += 128) {
            int key = i >> 3, c4 = (i & 7) << 2;
            const float* src = g_qkv + (size_t)(kt * 32 + key) * 384 + 128 + head * 32 + c4;
            *(float4*)(Ks + key * 36 + c4) = *(const float4*)src;
            *(float4*)(Vs + key * 40 + c4) = *(const float4*)(src + 128);
        }
        __syncthreads();

        // S = Q * K^T  (split-tf32: hi*hi + lo*hi + hi*lo)
        float S[4][4];
#pragma unroll
        for (int nn = 0; nn < 4; nn++)
#pragma unroll
            for (int i = 0; i < 4; i++) S[nn][i] = 0.f;
#pragma unroll
        for (int kk = 0; kk < 4; kk++) {
#pragma unroll
            for (int nn = 0; nn < 4; nn++) {
                float kb0 = Ks[(nn * 8 + g) * 36 + kk * 8 + tg];
                float kb1 = Ks[(nn * 8 + g) * 36 + kk * 8 + tg + 4];
                uint32_t bh[2], bl[2];
                split_tf32(kb0, bh[0], bl[0]);
                split_tf32(kb1, bh[1], bl[1]);
                mma_tf32(S[nn], qhi[kk], bh);
                mma_tf32(S[nn], qlo[kk], bh);
                mma_tf32(S[nn], qhi[kk], bl);
            }
        }

        // online softmax. lane holds rows {g, g+8}, cols {8nn+2tg, +1}
        float mx0 = fmaxf(S[0][0], S[0][1]);
        float mx1 = fmaxf(S[0][2], S[0][3]);
#pragma unroll
        for (int nn = 1; nn < 4; nn++) {
            mx0 = fmaxf(mx0, fmaxf(S[nn][0], S[nn][1]));
            mx1 = fmaxf(mx1, fmaxf(S[nn][2], S[nn][3]));
        }
        mx0 = fmaxf(mx0, __shfl_xor_sync(0xffffffffu, mx0, 1));
        mx0 = fmaxf(mx0, __shfl_xor_sync(0xffffffffu, mx0, 2));
        mx1 = fmaxf(mx1, __shfl_xor_sync(0xffffffffu, mx1, 1));
        mx1 = fmaxf(mx1, __shfl_xor_sync(0xffffffffu, mx1, 2));
        float nm0 = fmaxf(m0, mx0), nm1 = fmaxf(m1, mx1);
        float c0 = __expf(m0 - nm0), c1 = __expf(m1 - nm1);
        m0 = nm0; m1 = nm1;
        l0 *= c0; l1 *= c1;
#pragma unroll
        for (int nn = 0; nn < 4; nn++) {
            O[nn][0] *= c0; O[nn][1] *= c0;
            O[nn][2] *= c1; O[nn][3] *= c1;
        }
#pragma unroll
        for (int nn = 0; nn < 4; nn++) {
            // truncate p to tf32 BEFORE summing into l: bias cancels in O/l
            float p0 = trunc_tf32(__expf(S[nn][0] - m0));
            float p1 = trunc_tf32(__expf(S[nn][1] - m0));
            float p2 = trunc_tf32(__expf(S[nn][2] - m1));
            float p3 = trunc_tf32(__expf(S[nn][3] - m1));
            l0 += p0 + p1;
            l1 += p2 + p3;
            *(float2*)(Pw + g * 36 + nn * 8 + 2 * tg) = make_float2(p0, p1);
            *(float2*)(Pw + (g + 8) * 36 + nn * 8 + 2 * tg) = make_float2(p2, p3);
        }
        __syncwarp();

        // O += P * V
#pragma unroll
        for (int kk = 0; kk < 4; kk++) {
            uint32_t a[4];
            a[0] = __float_as_uint(Pw[g * 36 + kk * 8 + tg]);
            a[1] = __float_as_uint(Pw[(g + 8) * 36 + kk * 8 + tg]);
            a[2] = __float_as_uint(Pw[g * 36 + kk * 8 + tg + 4]);
            a[3] = __float_as_uint(Pw[(g + 8) * 36 + kk * 8 + tg + 4]);
#pragma unroll
            for (int nn = 0; nn < 4; nn++) {
                uint32_t b[2];
                b[0] = __float_as_uint(Vs[(kk * 8 + tg) * 40 + nn * 8 + g]);
                b[1] = __float_as_uint(Vs[(kk * 8 + tg + 4) * 40 + nn * 8 + g]);
                mma_tf32(O[nn], a, b);
            }
        }
    }

    l0 += __shfl_xor_sync(0xffffffffu, l0, 1);
    l0 += __shfl_xor_sync(0xffffffffu, l0, 2);
    l1 += __shfl_xor_sync(0xffffffffu, l1, 1);
    l1 += __shfl_xor_sync(0xffffffffu, l1, 2);
    float i0 = 1.f / l0, i1 = 1.f / l1;
#pragma unroll
    for (int nn = 0; nn < 4; nn++) {
        *(float2*)(g_att + (size_t)(q0 + g) * HID + head * 32 + nn * 8 + 2 * tg) =
            make_float2(O[nn][0] * i0, O[nn][1] * i0);
        *(float2*)(g_att + (size_t)(q0 + g + 8) * HID + head * 32 + nn * 8 + 2 * tg) =
            make_float2(O[nn][2] * i1, O[nn][3] * i1);
    }
}

// ---------------- epilogue ----------------
__global__ void __launch_bounds__(128) epi_kernel(
    const float* __restrict__ bout_att,
    const float* __restrict__ gw, const float* __restrict__ gb,
    const float* __restrict__ ow, const float* __restrict__ ob,
    float* __restrict__ out) {
    __shared__ float att[16][128];
    __shared__ float upd[16][128];
    __shared__ float osh[16][128];
    int t = threadIdx.x;
    int base = blockIdx.x * 16;
    for (int i = t; i < 2048; i += 128) {
        int a = i >> 7, d = i & 127;
        att[a][d] = g_att[(size_t)(base + a) * HID + d];
        upd[a][d] = g_upd[(size_t)(base + a) * HID + d];
    }
    __syncthreads();
    float ap[16];
#pragma unroll
    for (int a = 0; a < 16; a++) ap[a] = 0.f;
    for (int d = 0; d < 128; d++) {
        float wv = g_woutT[d * HID + t];
#pragma unroll
        for (int a = 0; a < 16; a++) ap[a] += att[a][d] * wv;
    }
    float ba = bout_att[t];
    float gacc[16];
#pragma unroll
    for (int a = 0; a < 16; a++) gacc[a] = 0.f;
    for (int d = 0; d < 128; d++) {
        float wv = gw[d * HID + t];
#pragma unroll
        for (int a = 0; a < 16; a++) gacc[a] += upd[a][d] * wv;
    }
    float bg = gb[t];
#pragma unroll
    for (int a = 0; a < 16; a++) {
        float g = 1.f / (1.f + __expf(-(gacc[a] + bg)));
        osh[a][t] = g * (ap[a] + ba) + (1.f - g) * upd[a][t];
    }
    __syncthreads();
    float f[16];
#pragma unroll
    for (int a = 0; a < 16; a++) f[a] = 0.f;
    for (int d = 0; d < 128; d++) {
        float wv = ow[d * HID + t];
#pragma unroll
        for (int a = 0; a < 16; a++) f[a] += osh[a][d] * wv;
    }
    float bo = ob[t];
#pragma unroll
    for (int a = 0; a < 16; a++)
        out[(size_t)(base + a) * HID + t] = f[a] + bo;
}

// ---------------- launch ----------------
extern "C" void kernel_launch(void* const* d_in, const int* in_sizes, int n_in,
                              void* d_out, int out_size) {
    const int* an = (const int*)d_in[0];
    const int* ei = (const int*)d_in[2];
    const float* ev = (const float*)d_in[3];
    const float* el = (const float*)d_in[4];
    const float* embed = (const float*)d_in[5];
    const float* rw1 = (const float*)d_in[6];
    const float* rb1 = (const float*)d_in[7];
    const float* rw2 = (const float*)d_in[8];
    const float* rb2 = (const float*)d_in[9];
    const float* tpw = (const float*)d_in[10];
    const float* tpb = (const float*)d_in[11];
    const float* mw1 = (const float*)d_in[12];
    const float* mb1 = (const float*)d_in[13];
    const float* mw2 = (const float*)d_in[14];
    const float* mb2 = (const float*)d_in[15];
    const float* win = (const float*)d_in[16];
    const float* bin = (const float*)d_in[17];
    const float* wout = (const float*)d_in[18];
    const float* bout = (const float*)d_in[19];
    const float* gw = (const float*)d_in[20];
    const float* gb = (const float*)d_in[21];
    const float* ow = (const float*)d_in[22];
    const float* obv = (const float*)d_in[23];
    float* out = (float*)d_out;

    const int* dst = ei + N_EDGES;

    zero_kernel<<<16, 256>>>();
    hist_kernel<<<256, 512>>>(dst);
    prep_kernel<<<256, 256>>>(tpw, win, wout);
    radtab_kernel<<<1025, 128>>>(rw1, rb1, rw2, rb2);
    scan_kernel<<<1, 1024>>>();
    scatter_kernel<<<256, 512>>>(dst);
    edge_agg_kernel<<<1024, 128>>>(ev, el);
    tp_gemm_kernel<<<128, 128>>>(tpb);
    upd_kernel<<<256, 128>>>(an, embed, mw1, mb1, mw2, mb2);
    qkv_kernel<<<256, 384>>>(bin);
    attn_mma_kernel<<<dim3(64, 4), 128>>>();
    epi_kernel<<<256, 128>>>(bout, gw, gb, ow, obv, out);
}

// round 3
// speedup vs baseline: 3.5847x; 1.3566x over previous
#include <cuda_runtime.h>
#include <math.h>
#include <stdint.h>

#define N_ATOMS 4096
#define N_EDGES 131072
#define EMBED 64
#define HID 128
#define TP_IN 1152
#define NBINS 4096
#define D_LO 0.4f
#define D_HI 6.0f

// ---------------- scratch ----------------
__device__ __align__(16) float g_pre[N_ATOMS * TP_IN];
__device__ __align__(16) float g_agg[N_ATOMS * HID];
__device__ __align__(16) float g_upd[N_ATOMS * HID];
__device__ __align__(16) float g_qkv[N_ATOMS * 3 * HID];
__device__ __align__(16) float g_kT[N_ATOMS * HID];   // K rounded to tf32
__device__ __align__(16) float g_vT[N_ATOMS * HID];   // V rounded to tf32
__device__ __align__(16) float g_att[N_ATOMS * HID];
__device__ __align__(16) float g_tpw[TP_IN * HID];    // permuted + tf32-rounded
__device__ __align__(16) float g_wqkvT[HID * 3 * HID];
__device__ __align__(16) float g_woutT[HID * HID];
__device__ __align__(16) float g_radtab[(NBINS + 1) * HID];
__device__ int g_count[N_ATOMS];
__device__ int g_offset[N_ATOMS + 1];
__device__ int g_cursor[N_ATOMS];
__device__ int g_eperm[N_EDGES];

// ---------------- helpers ----------------
__device__ __forceinline__ void mma_tf32(float* d, const uint32_t* a, const uint32_t* b) {
    asm volatile(
        "mma.sync.aligned.m16n8k8.row.col.f32.tf32.tf32.f32 "
        "{%0,%1,%2,%3},{%4,%5,%6,%7},{%8,%9},{%0,%1,%2,%3};\n"
        : "+f"(d[0]), "+f"(d[1]), "+f"(d[2]), "+f"(d[3])
        : "r"(a[0]), "r"(a[1]), "r"(a[2]), "r"(a[3]), "r"(b[0]), "r"(b[1]));
}
__device__ __forceinline__ void split_tf32(float x, uint32_t& hi, uint32_t& lo) {
    uint32_t h = __float_as_uint(x) & 0xFFFFE000u;
    hi = h;
    lo = __float_as_uint(x - __uint_as_float(h));
}
__device__ __forceinline__ float rna_tf32(float x) {
    uint32_t r;
    asm("cvt.rna.tf32.f32 %0, %1;" : "=r"(r) : "f"(x));
    return __uint_as_float(r);
}
__device__ __forceinline__ void cp16(uint32_t dst, const void* src) {
    asm volatile("cp.async.cg.shared.global [%0], [%1], 16;\n" :: "r"(dst), "l"(src));
}
#define CP_COMMIT asm volatile("cp.async.commit_group;\n" ::: "memory")
#define CP_WAIT0  asm volatile("cp.async.wait_group 0;\n" ::: "memory")

// ---------------- CSR build ----------------
__global__ void zero_kernel() {
    int i = blockIdx.x * blockDim.x + threadIdx.x;
    if (i < N_ATOMS) g_count[i] = 0;
}
__global__ void hist_kernel(const int* __restrict__ dst) {
    int i = blockIdx.x * blockDim.x + threadIdx.x;
    if (i < N_EDGES) atomicAdd(&g_count[dst[i]], 1);
}
__global__ void scan_kernel() {
    __shared__ int buf0[N_ATOMS];
    __shared__ int buf1[N_ATOMS];
    int t = threadIdx.x;
    for (int i = t; i < N_ATOMS; i += 1024) buf0[i] = g_count[i];
    __syncthreads();
    int* cur = buf0;
    int* nxt = buf1;
    for (int off = 1; off < N_ATOMS; off <<= 1) {
        for (int i = t; i < N_ATOMS; i += 1024) {
            int v = cur[i];
            if (i >= off) v += cur[i - off];
            nxt[i] = v;
        }
        __syncthreads();
        int* tmp = cur; cur = nxt; nxt = tmp;
    }
    for (int i = t; i < N_ATOMS; i += 1024) {
        g_offset[i + 1] = cur[i];
        g_cursor[i] = (i == 0) ? 0 : cur[i - 1];
    }
    if (t == 0) g_offset[0] = 0;
}
__global__ void scatter_kernel(const int* __restrict__ dst) {
    int i = blockIdx.x * blockDim.x + threadIdx.x;
    if (i < N_EDGES) {
        int p = atomicAdd(&g_cursor[dst[i]], 1);
        g_eperm[p] = i;
    }
}

// ---------------- weight prep ----------------
__global__ void prep_kernel(const float* __restrict__ tpw,
                            const float* __restrict__ win,
                            const float* __restrict__ wout) {
    int idx = blockIdx.x * blockDim.x + threadIdx.x;
    int stride = gridDim.x * blockDim.x;
    for (int i = idx; i < TP_IN * HID; i += stride) {
        int rp = i >> 7;
        int c = i & 127;
        int s = rp >> 7;
        int h = rp & 127;
        int row;
        if (s == 0)      row = h;
        else if (s <= 3) row = 128 + h * 3 + (s - 1);
        else             row = 512 + h * 5 + (s - 4);
        g_tpw[i] = rna_tf32(tpw[row * HID + c]);  // pre-round weights for tf32 mma
    }
    for (int i = idx; i < HID * 3 * HID; i += stride) {
        int d = i / 384, j = i % 384;
        g_wqkvT[i] = win[j * HID + d];
    }
    for (int i = idx; i < HID * HID; i += stride) {
        int d = i >> 7, j = i & 127;
        g_woutT[i] = wout[j * HID + d];
    }
}

// ---------------- radial table (32 bins / block, weights loaded once) --------
__global__ void __launch_bounds__(128) radtab_kernel(
    const float* __restrict__ rw1, const float* __restrict__ rb1,
    const float* __restrict__ rw2, const float* __restrict__ rb2) {
    __shared__ float w1s[8 * 64];
    __shared__ float w2s[64 * 128];
    __shared__ float b1s[64];
    __shared__ float b2s[128];
    __shared__ float r1s[4][64];

    int t = threadIdx.x;
    for (int i = t; i < 512; i += 128) w1s[i] = rw1[i];
    for (int i = t; i < 8192; i += 128) w2s[i] = rw2[i];
    if (t < 64) b1s[t] = rb1[t];
    b2s[t] = rb2[t];
    __syncthreads();

    int w = t >> 5, lane = t & 31;
    const float h = (D_HI - D_LO) / (float)NBINS;
    const float FP = 3.14159265358979323846f / 6.0f;

    for (int it = 0; it < 8; it++) {
        int bin = blockIdx.x * 32 + it * 4 + w;
        if (bin > NBINS) continue;
        float d = D_LO + bin * h;
        float cut = 0.5f * (cosf(d * FP) + 1.f) * (d < 6.0f ? 1.f : 0.f);
        float invd = cut / d;
        float rbf[8];
#pragma unroll
        for (int i = 0; i < 8; i++) rbf[i] = sinf(d * (FP * (i + 1))) * invd;

        float a0 = b1s[lane], a1 = b1s[lane + 32];
#pragma unroll
        for (int i = 0; i < 8; i++) {
            a0 += rbf[i] * w1s[i * 64 + lane];
            a1 += rbf[i] * w1s[i * 64 + lane + 32];
        }
        a0 = a0 / (1.f + __expf(-a0));
        a1 = a1 / (1.f + __expf(-a1));
        r1s[w][lane] = a0;
        r1s[w][lane + 32] = a1;
        __syncwarp();

        float r2[4];
#pragma unroll
        for (int k = 0; k < 4; k++) r2[k] = b2s[k * 32 + lane];
#pragma unroll 8
        for (int j = 0; j < 64; j++) {
            float rj = r1s[w][j];
#pragma unroll
            for (int k = 0; k < 4; k++) r2[k] += rj * w2s[j * 128 + k * 32 + lane];
        }
        __syncwarp();
#pragma unroll
        for (int k = 0; k < 4; k++) {
            float v = r2[k];
            v = v / (1.f + __expf(-v));
            g_radtab[bin * HID + k * 32 + lane] = v;
        }
    }
}

// ---------------- per-atom edge aggregation via table lerp ----------------
__global__ void __launch_bounds__(128) edge_agg_kernel(
    const float* __restrict__ ev, const float* __restrict__ el) {
    int t = threadIdx.x;
    int w = t >> 5, lane = t & 31;
    int atom = blockIdx.x * 4 + w;
    int start = g_offset[atom];
    int end = g_offset[atom + 1];

    float acc[4][9];
#pragma unroll
    for (int k = 0; k < 4; k++)
#pragma unroll
        for (int s = 0; s < 9; s++) acc[k][s] = 0.f;

    const float INV_H = (float)NBINS / (D_HI - D_LO);

    for (int idx = start; idx < end; ++idx) {
        int e = g_eperm[idx];
        float vx = __ldg(ev + e * 3 + 0);
        float vy = __ldg(ev + e * 3 + 1);
        float vz = __ldg(ev + e * 3 + 2);
        float d = __ldg(el + e);
        float r = sqrtf(vx * vx + vy * vy + vz * vz) + 1e-8f;
        float inv = 1.f / r;
        float x = vx * inv, y = vy * inv, z = vz * inv;
        float sh[9];
        sh[0] = 1.f; sh[1] = y; sh[2] = z; sh[3] = x;
        sh[4] = 3.f * z * z - 1.f; sh[5] = x * z; sh[6] = y * z;
        sh[7] = x * y; sh[8] = x * x - y * y;

        float tt = (d - D_LO) * INV_H;
        int i0 = (int)tt;
        i0 = min(max(i0, 0), NBINS - 1);
        float f = tt - (float)i0;
        const float* r0 = g_radtab + (size_t)i0 * HID;

#pragma unroll
        for (int k = 0; k < 4; k++) {
            int c = k * 32 + lane;
            float lo = r0[c];
            float hi = r0[c + HID];
            float ra = fmaf(f, hi - lo, lo);
#pragma unroll
            for (int s = 0; s < 9; s++) acc[k][s] += ra * sh[s];
        }
    }

#pragma unroll
    for (int k = 0; k < 4; k++)
#pragma unroll
        for (int s = 0; s < 9; s++)
            g_pre[(size_t)atom * TP_IN + s * 128 + k * 32 + lane] = acc[k][s];
}

// ---------------- tf32 mma tp-GEMM: agg = pre @ tpw + deg*b  ----------------
// grid 128 blocks x 128 thr; block = 32 rows x 128 cols; warp = 16 rows x 64 cols
__global__ void __launch_bounds__(128) tp_mma_kernel(const float* __restrict__ tpb) {
    __shared__ __align__(16) float As[2][32 * 20];
    __shared__ __align__(16) float Bs[2][16 * 136];
    const int t = threadIdx.x;
    const int warp = t >> 5, lane = t & 31;
    const int g = lane >> 2, tg = lane & 3;
    const int rows0 = blockIdx.x * 32;
    const int rloc = (warp & 1) * 16;
    const int c0 = (warp >> 1) * 64;

    uint32_t as_base = (uint32_t)__cvta_generic_to_shared(As);
    uint32_t bs_base = (uint32_t)__cvta_generic_to_shared(Bs);

    float C[8][4];
#pragma unroll
    for (int nn = 0; nn < 8; nn++)
#pragma unroll
        for (int i = 0; i < 4; i++) C[nn][i] = 0.f;

    // prologue: chunk 0
    {
        int r = t >> 2, ch = (t & 3) * 4;
        cp16(as_base + (r * 20 + ch) * 4, g_pre + (size_t)(rows0 + r) * TP_IN + ch);
#pragma unroll
        for (int i = t; i < 512; i += 128) {
            int kr = i >> 5, c = (i & 31) * 4;
            cp16(bs_base + (kr * 136 + c) * 4, g_tpw + (size_t)kr * HID + c);
        }
        CP_COMMIT;
    }

    for (int kc = 0; kc < 72; kc++) {
        CP_WAIT0;
        __syncthreads();
        int buf = kc & 1;
        if (kc + 1 < 72) {
            int nb = buf ^ 1;
            int r = t >> 2, ch = (t & 3) * 4;
            cp16(as_base + (nb * 640 + r * 20 + ch) * 4,
                 g_pre + (size_t)(rows0 + r) * TP_IN + (kc + 1) * 16 + ch);
#pragma unroll
            for (int i = t; i < 512; i += 128) {
                int kr = i >> 5, c = (i & 31) * 4;
                cp16(bs_base + (nb * 2176 + kr * 136 + c) * 4,
                     g_tpw + (size_t)((kc + 1) * 16 + kr) * HID + c);
            }
            CP_COMMIT;
        }
#pragma unroll
        for (int k8 = 0; k8 < 2; k8++) {
            int k0 = k8 * 8;
            float av0 = As[buf][(rloc + g) * 20 + k0 + tg];
            float av1 = As[buf][(rloc + g + 8) * 20 + k0 + tg];
            float av2 = As[buf][(rloc + g) * 20 + k0 + tg + 4];
            float av3 = As[buf][(rloc + g + 8) * 20 + k0 + tg + 4];
            uint32_t ahi[4], alo[4];
            split_tf32(av0, ahi[0], alo[0]);
            split_tf32(av1, ahi[1], alo[1]);
            split_tf32(av2, ahi[2], alo[2]);
            split_tf32(av3, ahi[3], alo[3]);
#pragma unroll
            for (int nn = 0; nn < 8; nn++) {
                uint32_t b[2];
                b[0] = __float_as_uint(Bs[buf][(k0 + tg) * 136 + c0 + nn * 8 + g]);
                b[1] = __float_as_uint(Bs[buf][(k0 + tg + 4) * 136 + c0 + nn * 8 + g]);
                mma_tf32(C[nn], ahi, b);
                mma_tf32(C[nn], alo, b);
            }
        }
        __syncthreads();
    }

    int gr0 = rows0 + rloc + g;
    int gr1 = gr0 + 8;
    float deg0 = (float)g_count[gr0];
    float deg1 = (float)g_count[gr1];
#pragma unroll
    for (int nn = 0; nn < 8; nn++) {
        int col = c0 + nn * 8 + 2 * tg;
        float b0 = tpb[col], b1 = tpb[col + 1];
        *(float2*)(g_agg + (size_t)gr0 * HID + col) =
            make_float2(C[nn][0] + deg0 * b0, C[nn][1] + deg0 * b1);
        *(float2*)(g_agg + (size_t)gr1 * HID + col) =
            make_float2(C[nn][2] + deg1 * b0, C[nn][3] + deg1 * b1);
    }
}

// ---------------- upd MLP ----------------
__global__ void __launch_bounds__(128) upd_kernel(
    const int* __restrict__ an, const float* __restrict__ embed,
    const float* __restrict__ mw1, const float* __restrict__ mb1,
    const float* __restrict__ mw2, const float* __restrict__ mb2) {
    __shared__ float comb[16][192];
    __shared__ float t1[16][128];
    __shared__ int ans[16];
    int t = threadIdx.x;
    int base = blockIdx.x * 16;
    if (t < 16) ans[t] = an[base + t];
    __syncthreads();
    for (int i = t; i < 16 * 64; i += 128) {
        int a = i >> 6, d = i & 63;
        comb[a][d] = embed[ans[a] * 64 + d];
    }
    for (int i = t; i < 16 * 128; i += 128) {
        int a = i >> 7, d = i & 127;
        comb[a][64 + d] = g_agg[(size_t)(base + a) * HID + d];
    }
    __syncthreads();
    float acc[16];
#pragma unroll
    for (int a = 0; a < 16; a++) acc[a] = 0.f;
    for (int d = 0; d < 192; d++) {
        float wv = mw1[d * HID + t];
#pragma unroll
        for (int a = 0; a < 16; a++) acc[a] += comb[a][d] * wv;
    }
    float b1 = mb1[t];
#pragma unroll
    for (int a = 0; a < 16; a++) {
        float v = acc[a] + b1;
        t1[a][t] = v / (1.f + __expf(-v));
    }
    __syncthreads();
#pragma unroll
    for (int a = 0; a < 16; a++) acc[a] = 0.f;
    for (int d = 0; d < 128; d++) {
        float wv = mw2[d * HID + t];
#pragma unroll
        for (int a = 0; a < 16; a++) acc[a] += t1[a][d] * wv;
    }
    float b2 = mb2[t];
#pragma unroll
    for (int a = 0; a < 16; a++)
        g_upd[(size_t)(base + a) * HID + t] = acc[a] + b2;
}

// ---------------- qkv: Q -> g_qkv; K,V -> rounded tf32 planes ----------------
__global__ void __launch_bounds__(384) qkv_kernel(const float* __restrict__ bqkv) {
    __shared__ float u[16][128];
    int t = threadIdx.x;
    int base = blockIdx.x * 16;
    for (int i = t; i < 2048; i += 384) {
        int a = i >> 7, d = i & 127;
        u[a][d] = g_upd[(size_t)(base + a) * HID + d];
    }
    __syncthreads();
    float acc[16];
#pragma unroll
    for (int a = 0; a < 16; a++) acc[a] = 0.f;
    for (int d = 0; d < 128; d++) {
        float wv = g_wqkvT[d * 384 + t];
#pragma unroll
        for (int a = 0; a < 16; a++) acc[a] += u[a][d] * wv;
    }
    float b = bqkv[t];
    if (t < 128) {
#pragma unroll
        for (int a = 0; a < 16; a++)
            g_qkv[(size_t)(base + a) * 384 + t] = acc[a] + b;
    } else if (t < 256) {
#pragma unroll
        for (int a = 0; a < 16; a++)
            g_kT[(size_t)(base + a) * HID + (t - 128)] = rna_tf32(acc[a] + b);
    } else {
#pragma unroll
        for (int a = 0; a < 16; a++)
            g_vT[(size_t)(base + a) * HID + (t - 256)] = rna_tf32(acc[a] + b);
    }
}

// ---------------- tf32 mma flash attention, 64-key tiles, double-buffered ----
__global__ void __launch_bounds__(128) attn_mma_kernel() {
    __shared__ __align__(16) float Ks[2][64 * 36];
    __shared__ __align__(16) float Vs[2][64 * 40];
    const int t = threadIdx.x;
    const int warp = t >> 5, lane = t & 31;
    const int g = lane >> 2, tg = lane & 3;
    const int head = blockIdx.y;
    const int q0 = blockIdx.x * 64 + warp * 16;
    const float scale = 0.17677669529663687f;

    uint32_t ks_base = (uint32_t)__cvta_generic_to_shared(Ks);
    uint32_t vs_base = (uint32_t)__cvta_generic_to_shared(Vs);

    // Q fragments, split hi/lo (exact)
    uint32_t qhi[4][4], qlo[4][4];
#pragma unroll
    for (int kk = 0; kk < 4; kk++) {
        const float* qp = g_qkv + (size_t)(q0 + g) * 384 + head * 32 + kk * 8;
        const float* qp8 = qp + 8 * 384;
        split_tf32(qp[tg] * scale, qhi[kk][0], qlo[kk][0]);
        split_tf32(qp8[tg] * scale, qhi[kk][1], qlo[kk][1]);
        split_tf32(qp[tg + 4] * scale, qhi[kk][2], qlo[kk][2]);
        split_tf32(qp8[tg + 4] * scale, qhi[kk][3], qlo[kk][3]);
    }

    float O[4][4];
#pragma unroll
    for (int nn = 0; nn < 4; nn++)
#pragma unroll
        for (int i = 0; i < 4; i++) O[nn][i] = 0.f;
    float m0 = -1e30f, m1 = -1e30f, l0 = 0.f, l1 = 0.f;

    // prologue: load tile 0
#pragma unroll
    for (int i = t; i < 512; i += 128) {
        int key = i >> 3, ch = (i & 7) * 4;
        const float* src = g_kT + (size_t)key * HID + head * 32 + ch;
        cp16(ks_base + (key * 36 + ch) * 4, src);
        cp16(vs_base + (key * 40 + ch) * 4, g_vT + (size_t)key * HID + head * 32 + ch);
    }
    CP_COMMIT;

    for (int kt = 0; kt < 64; kt++) {
        CP_WAIT0;
        __syncthreads();
        int buf = kt & 1;
        if (kt + 1 < 64) {
            int nb = buf ^ 1;
#pragma unroll
            for (int i = t; i < 512; i += 128) {
                int key = i >> 3, ch = (i & 7) * 4;
                size_t row = (size_t)((kt + 1) * 64 + key) * HID + head * 32 + ch;
                cp16(ks_base + (nb * 64 * 36 + key * 36 + ch) * 4, g_kT + row);
                cp16(vs_base + (nb * 64 * 40 + key * 40 + ch) * 4, g_vT + row);
            }
            CP_COMMIT;
        }

        // S = Q * K^T (2-mma: qhi + qlo against rounded K)
        float S[8][4];
#pragma unroll
        for (int nn = 0; nn < 8; nn++)
#pragma unroll
            for (int i = 0; i < 4; i++) S[nn][i] = 0.f;
#pragma unroll
        for (int kk = 0; kk < 4; kk++) {
#pragma unroll
            for (int nn = 0; nn < 8; nn++) {
                uint32_t b[2];
                b[0] = __float_as_uint(Ks[buf][(nn * 8 + g) * 36 + kk * 8 + tg]);
                b[1] = __float_as_uint(Ks[buf][(nn * 8 + g) * 36 + kk * 8 + tg + 4]);
                mma_tf32(S[nn], qhi[kk], b);
                mma_tf32(S[nn], qlo[kk], b);
            }
        }

        // online softmax
        float mx0 = fmaxf(S[0][0], S[0][1]);
        float mx1 = fmaxf(S[0][2], S[0][3]);
#pragma unroll
        for (int nn = 1; nn < 8; nn++) {
            mx0 = fmaxf(mx0, fmaxf(S[nn][0], S[nn][1]));
            mx1 = fmaxf(mx1, fmaxf(S[nn][2], S[nn][3]));
        }
        mx0 = fmaxf(mx0, __shfl_xor_sync(0xffffffffu, mx0, 1));
        mx0 = fmaxf(mx0, __shfl_xor_sync(0xffffffffu, mx0, 2));
        mx1 = fmaxf(mx1, __shfl_xor_sync(0xffffffffu, mx1, 1));
        mx1 = fmaxf(mx1, __shfl_xor_sync(0xffffffffu, mx1, 2));
        float nm0 = fmaxf(m0, mx0), nm1 = fmaxf(m1, mx1);
        float c0 = __expf(m0 - nm0), c1 = __expf(m1 - nm1);
        m0 = nm0; m1 = nm1;
        l0 *= c0; l1 *= c1;
#pragma unroll
        for (int nn = 0; nn < 4; nn++) {
            O[nn][0] *= c0; O[nn][1] *= c0;
            O[nn][2] *= c1; O[nn][3] *= c1;
        }
#pragma unroll
        for (int nn = 0; nn < 8; nn++) {
            float p0 = rna_tf32(__expf(S[nn][0] - m0));
            float p1 = rna_tf32(__expf(S[nn][1] - m0));
            float p2 = rna_tf32(__expf(S[nn][2] - m1));
            float p3 = rna_tf32(__expf(S[nn][3] - m1));
            l0 += p0 + p1;
            l1 += p2 + p3;
            S[nn][0] = p0; S[nn][1] = p1; S[nn][2] = p2; S[nn][3] = p3;
        }

        // O += P * V ; P relayout via shuffles (S-frag -> A-frag)
        const int src = g * 4 + (tg >> 1);
        const int alt = src + 2;
        const bool oddc = (tg & 1);
#pragma unroll
        for (int kk = 0; kk < 8; kk++) {
            uint32_t a[4];
            float x0 = __shfl_sync(0xffffffffu, S[kk][0], src);
            float x1 = __shfl_sync(0xffffffffu, S[kk][1], src);
            a[0] = __float_as_uint(oddc ? x1 : x0);
            float x2 = __shfl_sync(0xffffffffu, S[kk][2], src);
            float x3 = __shfl_sync(0xffffffffu, S[kk][3], src);
            a[1] = __float_as_uint(oddc ? x3 : x2);
            float y0 = __shfl_sync(0xffffffffu, S[kk][0], alt);
            float y1 = __shfl_sync(0xffffffffu, S[kk][1], alt);
            a[2] = __float_as_uint(oddc ? y1 : y0);
            float y2 = __shfl_sync(0xffffffffu, S[kk][2], alt);
            float y3 = __shfl_sync(0xffffffffu, S[kk][3], alt);
            a[3] = __float_as_uint(oddc ? y3 : y2);
#pragma unroll
            for (int nn = 0; nn < 4; nn++) {
                uint32_t b[2];
                b[0] = __float_as_uint(Vs[buf][(kk * 8 + tg) * 40 + nn * 8 + g]);
                b[1] = __float_as_uint(Vs[buf][(kk * 8 + tg + 4) * 40 + nn * 8 + g]);
                mma_tf32(O[nn], a, b);
            }
        }
        __syncthreads();
    }

    l0 += __shfl_xor_sync(0xffffffffu, l0, 1);
    l0 += __shfl_xor_sync(0xffffffffu, l0, 2);
    l1 += __shfl_xor_sync(0xffffffffu, l1, 1);
    l1 += __shfl_xor_sync(0xffffffffu, l1, 2);
    float i0 = 1.f / l0, i1 = 1.f / l1;
#pragma unroll
    for (int nn = 0; nn < 4; nn++) {
        *(float2*)(g_att + (size_t)(q0 + g) * HID + head * 32 + nn * 8 + 2 * tg) =
            make_float2(O[nn][0] * i0, O[nn][1] * i0);
        *(float2*)(g_att + (size_t)(q0 + g + 8) * HID + head * 32 + nn * 8 + 2 * tg) =
            make_float2(O[nn][2] * i1, O[nn][3] * i1);
    }
}

// ---------------- epilogue ----------------
__global__ void __launch_bounds__(128) epi_kernel(
    const float* __restrict__ bout_att,
    const float* __restrict__ gw, const float* __restrict__ gb,
    const float* __restrict__ ow, const float* __restrict__ ob,
    float* __restrict__ out) {
    __shared__ float att[16][128];
    __shared__ float upd[16][128];
    __shared__ float osh[16][128];
    int t = threadIdx.x;
    int base = blockIdx.x * 16;
    for (int i = t; i < 2048; i += 128) {
        int a = i >> 7, d = i & 127;
        att[a][d] = g_att[(size_t)(base + a) * HID + d];
        upd[a][d] = g_upd[(size_t)(base + a) * HID + d];
    }
    __syncthreads();
    float ap[16];
#pragma unroll
    for (int a = 0; a < 16; a++) ap[a] = 0.f;
    for (int d = 0; d < 128; d++) {
        float wv = g_woutT[d * HID + t];
#pragma unroll
        for (int a = 0; a < 16; a++) ap[a] += att[a][d] * wv;
    }
    float ba = bout_att[t];
    float gacc[16];
#pragma unroll
    for (int a = 0; a < 16; a++) gacc[a] = 0.f;
    for (int d = 0; d < 128; d++) {
        float wv = gw[d * HID + t];
#pragma unroll
        for (int a = 0; a < 16; a++) gacc[a] += upd[a][d] * wv;
    }
    float bg = gb[t];
#pragma unroll
    for (int a = 0; a < 16; a++) {
        float g = 1.f / (1.f + __expf(-(gacc[a] + bg)));
        osh[a][t] = g * (ap[a] + ba) + (1.f - g) * upd[a][t];
    }
    __syncthreads();
    float f[16];
#pragma unroll
    for (int a = 0; a < 16; a++) f[a] = 0.f;
    for (int d = 0; d < 128; d++) {
        float wv = ow[d * HID + t];
#pragma unroll
        for (int a = 0; a < 16; a++) f[a] += osh[a][d] * wv;
    }
    float bo = ob[t];
#pragma unroll
    for (int a = 0; a < 16; a++)
        out[(size_t)(base + a) * HID + t] = f[a] + bo;
}

// ---------------- launch ----------------
extern "C" void kernel_launch(void* const* d_in, const int* in_sizes, int n_in,
                              void* d_out, int out_size) {
    const int* an = (const int*)d_in[0];
    const int* ei = (const int*)d_in[2];
    const float* ev = (const float*)d_in[3];
    const float* el = (const float*)d_in[4];
    const float* embed = (const float*)d_in[5];
    const float* rw1 = (const float*)d_in[6];
    const float* rb1 = (const float*)d_in[7];
    const float* rw2 = (const float*)d_in[8];
    const float* rb2 = (const float*)d_in[9];
    const float* tpw = (const float*)d_in[10];
    const float* tpb = (const float*)d_in[11];
    const float* mw1 = (const float*)d_in[12];
    const float* mb1 = (const float*)d_in[13];
    const float* mw2 = (const float*)d_in[14];
    const float* mb2 = (const float*)d_in[15];
    const float* win = (const float*)d_in[16];
    const float* bin = (const float*)d_in[17];
    const float* wout = (const float*)d_in[18];
    const float* bout = (const float*)d_in[19];
    const float* gw = (const float*)d_in[20];
    const float* gb = (const float*)d_in[21];
    const float* ow = (const float*)d_in[22];
    const float* obv = (const float*)d_in[23];
    float* out = (float*)d_out;

    const int* dst = ei + N_EDGES;

    zero_kernel<<<16, 256>>>();
    hist_kernel<<<256, 512>>>(dst);
    prep_kernel<<<256, 256>>>(tpw, win, wout);
    radtab_kernel<<<129, 128>>>(rw1, rb1, rw2, rb2);
    scan_kernel<<<1, 1024>>>();
    scatter_kernel<<<256, 512>>>(dst);
    edge_agg_kernel<<<1024, 128>>>(ev, el);
    tp_mma_kernel<<<128, 128>>>(tpb);
    upd_kernel<<<256, 128>>>(an, embed, mw1, mb1, mw2, mb2);
    qkv_kernel<<<256, 384>>>(bin);
    attn_mma_kernel<<<dim3(64, 4), 128>>>();
    epi_kernel<<<256, 128>>>(bout, gw, gb, ow, obv, out);
}